// round 14
// baseline (speedup 1.0000x reference)
#include <cuda_runtime.h>
#include <cuda_bf16.h>
#include <stdint.h>

// Problem dims
#define B_    4096
#define S_    128
#define E_    1024
#define H1D   4096
#define H2D   2048
#define NCLS  3

// s8 GEMM tiling: 128x128 CTA tile, 256 threads, warp grid 2(M) x 4(N), warp tile 64x32
// K chunk = 128 int8 elements = 128 bytes per row (SW128-style XOR swizzle)
#define BM 128
#define BN 128
#define CKB 128                              // K elements (=bytes) per chunk
#define A_TILE_B 16384                       // 128 rows * 128B (one digit)
#define B_TILE_B 16384                       // 128 rows * 128B
#define STAGE_B  (A_TILE_B + B_TILE_B)       // 32768
#define BIAS_B   1024
#define GEMM_DYN (BIAS_B + 2*STAGE_B)        // 66560

// ---------------- scratch (static device globals) ----------------
__device__ __align__(16) int8_t g_X2[(size_t)B_ * 2 * E_];    // pooled activation digits [d0|d1]
__device__ __align__(16) int8_t g_T1[(size_t)H1D * E_];       // ternary w1 int8
__device__ float                g_Y1[(size_t)B_ * H1D];
__device__ __align__(16) int8_t g_H1[(size_t)B_ * 2 * H1D];   // h1 digits [d0|d1]
__device__ __align__(16) int8_t g_T2[(size_t)H2D * H1D];      // ternary w2 int8
__device__ float                g_Y2[(size_t)B_ * H2D];
__device__ float                g_H2[(size_t)B_ * H2D];
__device__ float                g_T3[NCLS * H2D];
__device__ float                g_q1[B_];                     // per-row digit scale (layer1 input)
__device__ float                g_qh[B_];                     // per-row digit scale (layer2 input)
__device__ double               g_absum[3];
__device__ float                g_scales[3];

// ---------------- helpers ----------------
static __device__ __forceinline__ uint32_t smem_u32(const void* p) {
    return (uint32_t)__cvta_generic_to_shared(p);
}
static __device__ __forceinline__ void cp_async16(uint32_t s, const void* g) {
    asm volatile("cp.async.cg.shared.global [%0], [%1], 16;\n" :: "r"(s), "l"(g));
}
static __device__ __forceinline__ uint32_t pack4(float f0, float f1, float f2, float f3) {
    uint32_t w = (uint32_t)(uint8_t)(int8_t)__float2int_rn(f0);
    w |= (uint32_t)(uint8_t)(int8_t)__float2int_rn(f1) << 8;
    w |= (uint32_t)(uint8_t)(int8_t)__float2int_rn(f2) << 16;
    w |= (uint32_t)(uint8_t)(int8_t)__float2int_rn(f3) << 24;
    return w;
}

// ---------------- embedding gather + masked mean pool + digit quantization ------
// grid = B_ blocks of 256 threads; each block does a full row (256*4 = 1024 dims).
// Also zeroes g_absum (block 0) ahead of absum_all_kernel (stream-ordered).
__global__ __launch_bounds__(256)
void pool_kernel(const int* __restrict__ ids, const float* __restrict__ emb) {
    __shared__ int sid[S_];
    __shared__ int wcnt[4];
    __shared__ float rmax[256];
    const int b = blockIdx.x, t = threadIdx.x, lane = t & 31, w = t >> 5;
    if (b == 0 && t < 3) g_absum[t] = 0.0;

    if (w < 4) {   // threads 0..127 compact the nonzero ids, order preserved
        int id = ids[(size_t)b * S_ + t];
        unsigned m = __ballot_sync(0xFFFFFFFFu, id != 0);
        if (lane == 0) wcnt[w] = __popc(m);
        __syncwarp();
        if (id != 0) {
            // prefix over earlier warps via shared after they write: need sync first
            // (do the store after the block-wide sync below using saved values)
            sid[t] = 0;  // placeholder to keep smem initialized
        }
        // save per-thread compaction info in registers
        int keep = (id != 0);
        int inwarp = __popc(m & ((1u << lane) - 1u));
        // stash into shared after sync (see below) — use sid staging via registers:
        // we re-store after block sync using wcnt prefix
        __syncthreads();
        int base = 0;
#pragma unroll
        for (int i = 0; i < 4; i++) base += (i < w) ? wcnt[i] : 0;
        if (keep) sid[base + inwarp] = id;
    } else {
        __syncthreads();
    }
    __syncthreads();
    const int c = wcnt[0] + wcnt[1] + wcnt[2] + wcnt[3];

    const int d = t * 4;
    float a0 = 0.f, a1 = 0.f, a2 = 0.f, a3 = 0.f;
#pragma unroll 4
    for (int s = 0; s < c; s++) {
        float4 v = *(const float4*)(emb + (size_t)sid[s] * E_ + d);
        a0 += v.x; a1 += v.y; a2 += v.z; a3 += v.w;
    }
    float inv = 1.0f / (float)(c > 0 ? c : 1);
    float x[4] = {a0 * inv, a1 * inv, a2 * inv, a3 * inv};

    // block max of |x|
    float m4 = fmaxf(fmaxf(fabsf(x[0]), fabsf(x[1])), fmaxf(fabsf(x[2]), fabsf(x[3])));
    rmax[t] = m4;
    __syncthreads();
    for (int o = 128; o > 0; o >>= 1) {
        if (t < o) rmax[t] = fmaxf(rmax[t], rmax[t + o]);
        __syncthreads();
    }
    const float RM = rmax[0];
    const float q  = (RM > 0.f) ? RM * (1.0f / 127.0f) : 1.0f;
    const float iq = (RM > 0.f) ? 127.0f / RM : 0.0f;

    float d0[4], d1[4];
#pragma unroll
    for (int j = 0; j < 4; j++) {
        d0[j] = rintf(x[j] * iq);
        float r = x[j] - d0[j] * q;
        d1[j] = fminf(fmaxf(rintf(r * iq * 128.0f), -127.0f), 127.0f);
    }
    int8_t* dst = g_X2 + (size_t)b * 2 * E_;
    *(uint32_t*)(dst + d)      = pack4(d0[0], d0[1], d0[2], d0[3]);
    *(uint32_t*)(dst + E_ + d) = pack4(d1[0], d1[1], d1[2], d1[3]);
    if (t == 0) g_q1[b] = q;
}

// ---------------- abs-sum reduction ----------------
__global__ void absum_all_kernel(const float* __restrict__ w1,
                                 const float* __restrict__ w2,
                                 const float* __restrict__ w3) {
    __shared__ double red[256];
    const float* w; size_t n; int idx, bid, nb;
    if (blockIdx.x < 1024)      { w = w1; n = (size_t)H1D * E_;  idx = 0; bid = blockIdx.x;        nb = 1024; }
    else if (blockIdx.x < 2048) { w = w2; n = (size_t)H2D * H1D; idx = 1; bid = blockIdx.x - 1024; nb = 1024; }
    else                        { w = w3; n = NCLS * H2D;        idx = 2; bid = 0;                 nb = 1;    }
    double s = 0.0;
    for (size_t i = (size_t)bid * 256 + threadIdx.x; i < n; i += (size_t)nb * 256)
        s += (double)fabsf(w[i]);
    red[threadIdx.x] = s;
    __syncthreads();
    for (int o = 128; o > 0; o >>= 1) {
        if (threadIdx.x < o) red[threadIdx.x] += red[threadIdx.x + o];
        __syncthreads();
    }
    if (threadIdx.x == 0) atomicAdd(&g_absum[idx], red[0]);
}

// quantize all three weight tensors to int8 ternary; publishes g_scales
__global__ void quant_all_kernel(const float* __restrict__ w1,
                                 const float* __restrict__ w2,
                                 const float* __restrict__ w3) {
    const int n1 = H1D * E_;
    const int n2 = H2D * H1D;
    const int n3 = NCLS * H2D;
    const float s0 = (float)(g_absum[0] / (double)n1);
    const float s1 = (float)(g_absum[1] / (double)n2);
    const float s2 = (float)(g_absum[2] / (double)n3);
    if (blockIdx.x == 0 && threadIdx.x < 3)
        g_scales[threadIdx.x] = (threadIdx.x == 0) ? s0 : (threadIdx.x == 1 ? s1 : s2);
    const float i0 = 1.0f / s0;
    const float i1 = 1.0f / s1;
    const float i2 = 1.0f / s2;
    const int total = n1 + n2 + n3;
    for (int i = blockIdx.x * 256 + threadIdx.x; i < total; i += gridDim.x * 256) {
        if (i < n1) {
            float v = rintf(fminf(fmaxf(w1[i] * i0, -1.0f), 1.0f));
            g_T1[i] = (int8_t)(int)v;
        } else if (i < n1 + n2) {
            int k = i - n1;
            float v = rintf(fminf(fmaxf(w2[k] * i1, -1.0f), 1.0f));
            g_T2[k] = (int8_t)(int)v;
        } else {
            int k = i - n1 - n2;
            g_T3[k] = rintf(fminf(fmaxf(w3[k] * i2, -1.0f), 1.0f));
        }
    }
}

// ---------------- int8 digit GEMM ----------------
// C[M,N] = scale * q[m]/128 * (128*sum_k t*d0 + sum_k t*d1) + bias[n]
// A rows are [d0(K) | d1(K)] int8, stride 2K. Single int32 accumulator set:
// after the d0 phase (K elements), acc <<= 7, then d1 phase accumulates.
__global__ __launch_bounds__(256, 2)
void gemm_s8(const int8_t* __restrict__ A,
             const int8_t* __restrict__ Bw,
             const float* __restrict__ bias,
             const float* __restrict__ scale_p,
             const float* __restrict__ qrow,
             float* __restrict__ C, int N, int K) {
    extern __shared__ __align__(1024) char smem[];
    const uint32_t sb = smem_u32(smem) + BIAS_B;
    const int tid = threadIdx.x, lane = tid & 31, warp = tid >> 5;
    const int wm = warp & 1, wn = warp >> 1;      // 2 x 4 warps, warp tile 64x32
    const int bm = blockIdx.y * BM, bn = blockIdx.x * BN;
    const int KT = K / CKB;                        // chunks per digit phase
    const int CT = 2 * KT;                         // total chunks (d0 then d1)
    const size_t Astride = 2 * (size_t)K;

    for (int i = tid; i < BN; i += 256)
        *(float*)(smem + i * 4) = bias[bn + i];

    int acc[4][4][4];
#pragma unroll
    for (int i = 0; i < 4; i++)
#pragma unroll
        for (int j = 0; j < 4; j++)
#pragma unroll
            for (int v = 0; v < 4; v++) acc[i][j][v] = 0;

    auto load_stage = [&](int c) {
        const uint32_t base = sb + (uint32_t)(c & 1) * STAGE_B;
        const int ph = (c >= KT) ? 1 : 0;
        const int kc = c - ph * KT;
        const size_t aoff = (size_t)ph * K + (size_t)kc * CKB;
        const size_t boff = (size_t)kc * CKB;
        // A digit tile: 128 rows x 8 chunks (16B)
#pragma unroll
        for (int r = 0; r < 4; r++) {
            int idx = tid + r * 256;
            int row = idx >> 3, ch = idx & 7;
            uint32_t sw = row * 128 + ((ch ^ (row & 7)) << 4);
            cp_async16(base + sw, A + (size_t)(bm + row) * Astride + aoff + ch * 16);
        }
        // B tile: 128 rows x 8 chunks
#pragma unroll
        for (int r = 0; r < 4; r++) {
            int idx = tid + r * 256;
            int row = idx >> 3, ch = idx & 7;
            uint32_t sw = row * 128 + ((ch ^ (row & 7)) << 4);
            cp_async16(base + A_TILE_B + sw, Bw + (size_t)(bn + row) * K + boff + ch * 16);
        }
        asm volatile("cp.async.commit_group;\n" ::: "memory");
    };

    load_stage(0);

    for (int c = 0; c < CT; ++c) {
        asm volatile("cp.async.wait_group 0;\n" ::: "memory");
        __syncthreads();
        if (c + 1 < CT) load_stage(c + 1);

        const uint32_t base = sb + (uint32_t)(c & 1) * STAGE_B;
        const uint32_t Ab = base;
        const uint32_t Bb = base + A_TILE_B;

#pragma unroll
        for (int kk = 0; kk < 4; ++kk) {   // 4 x k32 per 128B chunk
            uint32_t b[4][2];
#pragma unroll
            for (int j = 0; j < 4; j++) {
                int row = wn * 32 + j * 8 + (lane & 7);
                int c2 = kk * 2 + ((lane >> 3) & 1);
                uint32_t addr = Bb + row * 128 + ((c2 ^ (row & 7)) << 4);
                asm volatile("ldmatrix.sync.aligned.m8n8.x2.shared.b16 {%0,%1}, [%2];\n"
                             : "=r"(b[j][0]), "=r"(b[j][1]) : "r"(addr));
            }
            uint32_t a[4][4];
#pragma unroll
            for (int i = 0; i < 4; i++) {
                int row = wm * 64 + i * 16 + (lane & 15);
                int c2 = kk * 2 + (lane >> 4);
                uint32_t addr = Ab + row * 128 + ((c2 ^ (row & 7)) << 4);
                asm volatile("ldmatrix.sync.aligned.m8n8.x4.shared.b16 {%0,%1,%2,%3}, [%4];\n"
                             : "=r"(a[i][0]), "=r"(a[i][1]), "=r"(a[i][2]), "=r"(a[i][3])
                             : "r"(addr));
            }
#pragma unroll
            for (int i = 0; i < 4; i++)
#pragma unroll
                for (int j = 0; j < 4; j++) {
                    asm volatile(
                        "mma.sync.aligned.m16n8k32.row.col.s32.s8.s8.s32 "
                        "{%0,%1,%2,%3}, {%4,%5,%6,%7}, {%8,%9}, {%0,%1,%2,%3};\n"
                        : "+r"(acc[i][j][0]), "+r"(acc[i][j][1]),
                          "+r"(acc[i][j][2]), "+r"(acc[i][j][3])
                        : "r"(a[i][0]), "r"(a[i][1]), "r"(a[i][2]), "r"(a[i][3]),
                          "r"(b[j][0]), "r"(b[j][1]));
                }
        }

        if (c == KT - 1) {   // end of d0 phase: acc = 128 * D0
#pragma unroll
            for (int i = 0; i < 4; i++)
#pragma unroll
                for (int j = 0; j < 4; j++)
#pragma unroll
                    for (int v = 0; v < 4; v++) acc[i][j][v] <<= 7;
        }
    }

    const float sc = *scale_p * (1.0f / 128.0f);
    const float* bsm = (const float*)smem;
#pragma unroll
    for (int i = 0; i < 4; i++) {
        int gm = bm + wm * 64 + i * 16 + (lane >> 2);
        float fa = sc * qrow[gm];
        float fb = sc * qrow[gm + 8];
#pragma unroll
        for (int j = 0; j < 4; j++) {
            int ln = wn * 32 + j * 8 + (lane & 3) * 2;
            int gn = bn + ln;
            float b0 = bsm[ln], b1 = bsm[ln + 1];
            C[(size_t)gm * N + gn]           = (float)acc[i][j][0] * fa + b0;
            C[(size_t)gm * N + gn + 1]       = (float)acc[i][j][1] * fa + b1;
            C[(size_t)(gm + 8) * N + gn]     = (float)acc[i][j][2] * fb + b0;
            C[(size_t)(gm + 8) * N + gn + 1] = (float)acc[i][j][3] * fb + b1;
        }
    }
}

// ---------------- LayerNorm + exact GELU -> int8 digits (layer 1) ----------------
// 256 threads, each owns 16 CONTIGUOUS cols. N = 4096.
__global__ __launch_bounds__(256)
void ln_gelu_q_kernel(const float* __restrict__ Y,
                      const float* __restrict__ gam,
                      const float* __restrict__ bet,
                      int N,
                      int8_t* __restrict__ Hd,    // [row][2N] digits
                      float* __restrict__ qout) {
    __shared__ float red[256];
    const int row = blockIdx.x, t = threadIdx.x;
    const float* y = Y + (size_t)row * N + t * 16;
    float v[16];
#pragma unroll
    for (int i = 0; i < 4; i++) {
        float4 f = *(const float4*)(y + i * 4);
        v[i * 4] = f.x; v[i * 4 + 1] = f.y; v[i * 4 + 2] = f.z; v[i * 4 + 3] = f.w;
    }
    float s = 0.f;
#pragma unroll
    for (int i = 0; i < 16; i++) s += v[i];
    red[t] = s; __syncthreads();
    for (int o = 128; o > 0; o >>= 1) { if (t < o) red[t] += red[t + o]; __syncthreads(); }
    float mu = red[0] / (float)N;
    __syncthreads();
    float qs = 0.f;
#pragma unroll
    for (int i = 0; i < 16; i++) { float dd = v[i] - mu; qs += dd * dd; }
    red[t] = qs; __syncthreads();
    for (int o = 128; o > 0; o >>= 1) { if (t < o) red[t] += red[t + o]; __syncthreads(); }
    float rstd = rsqrtf(red[0] / (float)N + 1e-5f);
    __syncthreads();

    float ge[16];
    float mx = 0.f;
#pragma unroll
    for (int i = 0; i < 16; i++) {
        int col = t * 16 + i;
        float h = (v[i] - mu) * rstd * gam[col] + bet[col];
        ge[i] = 0.5f * h * (1.0f + erff(h * 0.70710678118654752440f));
        mx = fmaxf(mx, fabsf(ge[i]));
    }
    red[t] = mx; __syncthreads();
    for (int o = 128; o > 0; o >>= 1) { if (t < o) red[t] = fmaxf(red[t], red[t + o]); __syncthreads(); }
    const float RM = red[0];
    const float q  = (RM > 0.f) ? RM * (1.0f / 127.0f) : 1.0f;
    const float iq = (RM > 0.f) ? 127.0f / RM : 0.0f;

    float d0[16], d1[16];
#pragma unroll
    for (int i = 0; i < 16; i++) {
        d0[i] = rintf(ge[i] * iq);
        float r = ge[i] - d0[i] * q;
        d1[i] = fminf(fmaxf(rintf(r * iq * 128.0f), -127.0f), 127.0f);
    }
    int8_t* dst = Hd + (size_t)row * 2 * N + t * 16;
    uint4 w0, w1;
    w0.x = pack4(d0[0], d0[1], d0[2], d0[3]);
    w0.y = pack4(d0[4], d0[5], d0[6], d0[7]);
    w0.z = pack4(d0[8], d0[9], d0[10], d0[11]);
    w0.w = pack4(d0[12], d0[13], d0[14], d0[15]);
    w1.x = pack4(d1[0], d1[1], d1[2], d1[3]);
    w1.y = pack4(d1[4], d1[5], d1[6], d1[7]);
    w1.z = pack4(d1[8], d1[9], d1[10], d1[11]);
    w1.w = pack4(d1[12], d1[13], d1[14], d1[15]);
    *(uint4*)dst       = w0;
    *(uint4*)(dst + N) = w1;
    if (t == 0) qout[row] = q;
}

// ---------------- LayerNorm + exact GELU -> fp32 (layer 2) ----------------
__global__ void ln_gelu_f_kernel(const float* __restrict__ Y,
                                 const float* __restrict__ gam,
                                 const float* __restrict__ bet,
                                 int N,
                                 float* __restrict__ Hf) {
    __shared__ float red[256];
    int row = blockIdx.x, t = threadIdx.x;
    const float* y = Y + (size_t)row * N;
    float v[8];
    float s = 0.f;
#pragma unroll
    for (int i = 0; i < 8; i++) { v[i] = y[t + i * 256]; s += v[i]; }
    red[t] = s; __syncthreads();
    for (int o = 128; o > 0; o >>= 1) { if (t < o) red[t] += red[t + o]; __syncthreads(); }
    float mu = red[0] / (float)N;
    __syncthreads();
    float qv = 0.f;
#pragma unroll
    for (int i = 0; i < 8; i++) { float d = v[i] - mu; qv += d * d; }
    red[t] = qv; __syncthreads();
    for (int o = 128; o > 0; o >>= 1) { if (t < o) red[t] += red[t + o]; __syncthreads(); }
    float rstd = rsqrtf(red[0] / (float)N + 1e-5f);
#pragma unroll
    for (int i = 0; i < 8; i++) {
        int col = t + i * 256;
        float h = (v[i] - mu) * rstd * gam[col] + bet[col];
        Hf[(size_t)row * N + col] = 0.5f * h * (1.0f + erff(h * 0.70710678118654752440f));
    }
}

// ---------------- final tiny layer (fp32) ----------------
__global__ void final_kernel(const float* __restrict__ b3, float* __restrict__ out) {
    __shared__ float red[NCLS][128];
    int row = blockIdx.x, t = threadIdx.x;   // 128 threads
    const float* h = g_H2 + (size_t)row * H2D;
    float a0 = 0.f, a1 = 0.f, a2 = 0.f;
    for (int k = t; k < H2D; k += 128) {
        float hv = h[k];
        a0 += hv * g_T3[k];
        a1 += hv * g_T3[H2D + k];
        a2 += hv * g_T3[2 * H2D + k];
    }
    red[0][t] = a0; red[1][t] = a1; red[2][t] = a2;
    __syncthreads();
    for (int o = 64; o > 0; o >>= 1) {
        if (t < o) {
            red[0][t] += red[0][t + o];
            red[1][t] += red[1][t + o];
            red[2][t] += red[2][t + o];
        }
        __syncthreads();
    }
    if (t < NCLS) out[row * NCLS + t] = g_scales[2] * red[t][0] + b3[t];
}

// ---------------- launch ----------------
extern "C" void kernel_launch(void* const* d_in, const int* in_sizes, int n_in,
                              void* d_out, int out_size) {
    const int*   ids = (const int*)d_in[0];
    const float* emb = (const float*)d_in[1];
    const float* w1  = (const float*)d_in[2];
    const float* b1  = (const float*)d_in[3];
    const float* w2  = (const float*)d_in[4];
    const float* b2  = (const float*)d_in[5];
    const float* w3  = (const float*)d_in[6];
    const float* b3  = (const float*)d_in[7];
    const float* g1  = (const float*)d_in[8];
    const float* be1 = (const float*)d_in[9];
    const float* g2  = (const float*)d_in[10];
    const float* be2 = (const float*)d_in[11];
    float* out = (float*)d_out;

    void *pX2, *pT1, *pY1, *pH1, *pT2, *pY2, *pH2, *pSc, *pQ1, *pQh;
    cudaGetSymbolAddress(&pX2, g_X2);
    cudaGetSymbolAddress(&pT1, g_T1);
    cudaGetSymbolAddress(&pY1, g_Y1);
    cudaGetSymbolAddress(&pH1, g_H1);
    cudaGetSymbolAddress(&pT2, g_T2);
    cudaGetSymbolAddress(&pY2, g_Y2);
    cudaGetSymbolAddress(&pH2, g_H2);
    cudaGetSymbolAddress(&pSc, g_scales);
    cudaGetSymbolAddress(&pQ1, g_q1);
    cudaGetSymbolAddress(&pQh, g_qh);

    cudaFuncSetAttribute(gemm_s8, cudaFuncAttributeMaxDynamicSharedMemorySize, GEMM_DYN);

    // launches 1-3: pool(+zero absum) + absum + quant; gemm1 is 4th (ncu -s 5 target)
    pool_kernel<<<B_, 256>>>(ids, emb);
    absum_all_kernel<<<2049, 256>>>(w1, w2, w3);
    quant_all_kernel<<<4096, 256>>>(w1, w2, w3);

    // 4) layer 1 GEMM (int8 digits): Y1 = s1*(X @ T1^T) + b1
    {
        dim3 grid(H1D / BN, B_ / BM);   // (32, 32)
        gemm_s8<<<grid, 256, GEMM_DYN>>>((const int8_t*)pX2, (const int8_t*)pT1,
                                         b1, (const float*)pSc + 0, (const float*)pQ1,
                                         (float*)pY1, H1D, E_);
    }
    ln_gelu_q_kernel<<<B_, 256>>>((const float*)pY1, g1, be1, H1D,
                                  (int8_t*)pH1, (float*)pQh);

    // layer 2 GEMM: Y2 = s2*(H1 @ T2^T) + b2
    {
        dim3 grid(H2D / BN, B_ / BM);   // (16, 32)
        gemm_s8<<<grid, 256, GEMM_DYN>>>((const int8_t*)pH1, (const int8_t*)pT2,
                                         b2, (const float*)pSc + 1, (const float*)pQh,
                                         (float*)pY2, H2D, H1D);
    }
    ln_gelu_f_kernel<<<B_, 256>>>((const float*)pY2, g2, be2, H2D, (float*)pH2);

    // final tiny layer
    final_kernel<<<B_, 128>>>(b3, out);
}